// round 1
// baseline (speedup 1.0000x reference)
#include <cuda_runtime.h>
#include <cuda_bf16.h>

// Problem shapes (fixed): B=4, S=2048, D_in=D_out=1024
#define BB 4
#define SS 2048
#define DD 1024
#define MQKV (BB * SS)          // 8192

// Scratch (device globals: allocation-free rule)
__device__ float g_Q[(size_t)MQKV * DD];       // 32 MB
__device__ float g_K[(size_t)MQKV * DD];       // 32 MB
__device__ float g_V[(size_t)MQKV * DD];       // 32 MB
__device__ float g_S[(size_t)BB * SS * SS];    // 64 MB (scores / probs)

// ---------------------------------------------------------------------------
// Tiled SGEMM: C[M,N] = alpha * A[M,K] @ B  (B either [K,N] or, TRANSB, [N,K])
// BM=BN=128, BK=16, 256 threads, 8x8 per thread (split 4+4 fragments).
// ---------------------------------------------------------------------------
#define BM 128
#define BN 128
#define BK 16
#define LDA (BM + 4)   // padded smem stride (keeps 16B alignment)
#define LDB (BN + 4)

template <bool TRANSB>
__global__ __launch_bounds__(256, 2)
void gemm_kernel(const float* __restrict__ A,
                 const float* __restrict__ B,
                 float* __restrict__ C,
                 int M, int N, int K,
                 size_t strideA, size_t strideB, size_t strideC,
                 float alpha)
{
    __shared__ float As[BK][LDA];
    __shared__ float Bs[BK][LDB];

    const int bz = blockIdx.z;
    A += (size_t)bz * strideA;
    B += (size_t)bz * strideB;
    C += (size_t)bz * strideC;

    const int tileM = blockIdx.y * BM;
    const int tileN = blockIdx.x * BN;

    const int tid = threadIdx.x;       // 0..255
    const int tx  = tid & 15;          // N direction
    const int ty  = tid >> 4;          // M direction

    float acc[8][8];
    #pragma unroll
    for (int i = 0; i < 8; i++)
        #pragma unroll
        for (int j = 0; j < 8; j++) acc[i][j] = 0.0f;

    for (int kt = 0; kt < K; kt += BK) {
        // ---- load A tile (BM x BK) transposed into As[k][m] ----
        #pragma unroll
        for (int i = 0; i < 2; i++) {
            int f    = tid + i * 256;        // 0..511 float4 units
            int row  = f >> 2;               // 0..127
            int colv = (f & 3) << 2;         // 0,4,8,12
            float4 v = *reinterpret_cast<const float4*>(
                &A[(size_t)(tileM + row) * K + kt + colv]);
            As[colv + 0][row] = v.x;
            As[colv + 1][row] = v.y;
            As[colv + 2][row] = v.z;
            As[colv + 3][row] = v.w;
        }
        // ---- load B tile into Bs[k][n] ----
        if (!TRANSB) {
            // B is [K,N]: rows kt..kt+15, contiguous along n
            #pragma unroll
            for (int i = 0; i < 2; i++) {
                int f    = tid + i * 256;
                int row  = f >> 5;             // 0..15 (k)
                int colv = (f & 31) << 2;      // 0..124 (n)
                float4 v = *reinterpret_cast<const float4*>(
                    &B[(size_t)(kt + row) * N + tileN + colv]);
                *reinterpret_cast<float4*>(&Bs[row][colv]) = v;
            }
        } else {
            // B is [N,K]: load along k, scatter-transpose into Bs[k][n]
            #pragma unroll
            for (int i = 0; i < 2; i++) {
                int f    = tid + i * 256;
                int row  = f >> 2;             // n: 0..127
                int colv = (f & 3) << 2;       // k
                float4 v = *reinterpret_cast<const float4*>(
                    &B[(size_t)(tileN + row) * K + kt + colv]);
                Bs[colv + 0][row] = v.x;
                Bs[colv + 1][row] = v.y;
                Bs[colv + 2][row] = v.z;
                Bs[colv + 3][row] = v.w;
            }
        }
        __syncthreads();

        // ---- compute: split fragments at +0 and +64 (conflict-free LDS.128) ----
        #pragma unroll
        for (int k = 0; k < BK; k++) {
            float ra[8], rb[8];
            *reinterpret_cast<float4*>(&ra[0]) =
                *reinterpret_cast<const float4*>(&As[k][ty * 4]);
            *reinterpret_cast<float4*>(&ra[4]) =
                *reinterpret_cast<const float4*>(&As[k][64 + ty * 4]);
            *reinterpret_cast<float4*>(&rb[0]) =
                *reinterpret_cast<const float4*>(&Bs[k][tx * 4]);
            *reinterpret_cast<float4*>(&rb[4]) =
                *reinterpret_cast<const float4*>(&Bs[k][64 + tx * 4]);
            #pragma unroll
            for (int m = 0; m < 8; m++)
                #pragma unroll
                for (int n = 0; n < 8; n++)
                    acc[m][n] = fmaf(ra[m], rb[n], acc[m][n]);
        }
        __syncthreads();
    }

    // ---- epilogue ----
    #pragma unroll
    for (int mh = 0; mh < 2; mh++) {
        #pragma unroll
        for (int mi = 0; mi < 4; mi++) {
            int m   = mh * 4 + mi;
            size_t row = (size_t)(tileM + mh * 64 + ty * 4 + mi);
            #pragma unroll
            for (int nh = 0; nh < 2; nh++) {
                float4 v;
                v.x = acc[m][nh * 4 + 0] * alpha;
                v.y = acc[m][nh * 4 + 1] * alpha;
                v.z = acc[m][nh * 4 + 2] * alpha;
                v.w = acc[m][nh * 4 + 3] * alpha;
                *reinterpret_cast<float4*>(
                    &C[row * N + tileN + nh * 64 + tx * 4]) = v;
            }
        }
    }
}

// ---------------------------------------------------------------------------
// Row softmax over 2048 cols, 1 block (256 threads) per row, data in registers
// ---------------------------------------------------------------------------
__global__ __launch_bounds__(256)
void softmax_kernel(float* __restrict__ S)
{
    __shared__ float sh[8];
    const size_t base = (size_t)blockIdx.x * SS;
    const int tid = threadIdx.x;
    float4* rowp = reinterpret_cast<float4*>(S + base);

    float4 v0 = rowp[tid];
    float4 v1 = rowp[tid + 256];

    // --- max reduce ---
    float m = fmaxf(fmaxf(fmaxf(v0.x, v0.y), fmaxf(v0.z, v0.w)),
                    fmaxf(fmaxf(v1.x, v1.y), fmaxf(v1.z, v1.w)));
    #pragma unroll
    for (int o = 16; o > 0; o >>= 1)
        m = fmaxf(m, __shfl_xor_sync(0xFFFFFFFFu, m, o));
    if ((tid & 31) == 0) sh[tid >> 5] = m;
    __syncthreads();
    m = sh[tid & 7];
    #pragma unroll
    for (int o = 4; o > 0; o >>= 1)
        m = fmaxf(m, __shfl_xor_sync(0xFFFFFFFFu, m, o));
    __syncthreads();

    // --- exp ---
    v0.x = __expf(v0.x - m); v0.y = __expf(v0.y - m);
    v0.z = __expf(v0.z - m); v0.w = __expf(v0.w - m);
    v1.x = __expf(v1.x - m); v1.y = __expf(v1.y - m);
    v1.z = __expf(v1.z - m); v1.w = __expf(v1.w - m);

    // --- sum reduce ---
    float s = (v0.x + v0.y + v0.z + v0.w) + (v1.x + v1.y + v1.z + v1.w);
    #pragma unroll
    for (int o = 16; o > 0; o >>= 1)
        s += __shfl_xor_sync(0xFFFFFFFFu, s, o);
    if ((tid & 31) == 0) sh[tid >> 5] = s;
    __syncthreads();
    s = sh[tid & 7];
    #pragma unroll
    for (int o = 4; o > 0; o >>= 1)
        s += __shfl_xor_sync(0xFFFFFFFFu, s, o);

    float inv = 1.0f / s;
    v0.x *= inv; v0.y *= inv; v0.z *= inv; v0.w *= inv;
    v1.x *= inv; v1.y *= inv; v1.z *= inv; v1.w *= inv;
    rowp[tid]       = v0;
    rowp[tid + 256] = v1;
}

// ---------------------------------------------------------------------------
// Launch
// ---------------------------------------------------------------------------
extern "C" void kernel_launch(void* const* d_in, const int* in_sizes, int n_in,
                              void* d_out, int out_size)
{
    const float* x  = (const float*)d_in[0];
    const float* WQ = (const float*)d_in[1];
    const float* WK = (const float*)d_in[2];
    const float* WV = (const float*)d_in[3];
    float* out = (float*)d_out;

    float *Q, *K, *V, *S;
    cudaGetSymbolAddress((void**)&Q, g_Q);
    cudaGetSymbolAddress((void**)&K, g_K);
    cudaGetSymbolAddress((void**)&V, g_V);
    cudaGetSymbolAddress((void**)&S, g_S);

    // 1) projections: [8192,1024] @ [1024,1024]
    dim3 gqkv(DD / BN, MQKV / BM, 1);
    gemm_kernel<false><<<gqkv, 256>>>(x, WQ, Q, MQKV, DD, DD, 0, 0, 0, 1.0f);
    gemm_kernel<false><<<gqkv, 256>>>(x, WK, K, MQKV, DD, DD, 0, 0, 0, 1.0f);
    gemm_kernel<false><<<gqkv, 256>>>(x, WV, V, MQKV, DD, DD, 0, 0, 0, 1.0f);

    // 2) scores: per batch, S = Q @ K^T / sqrt(D_in)  (scale = 32 exactly)
    dim3 gsc(SS / BN, SS / BM, BB);
    gemm_kernel<true><<<gsc, 256>>>(Q, K, S, SS, SS, DD,
                                    (size_t)SS * DD, (size_t)SS * DD,
                                    (size_t)SS * SS, 1.0f / 32.0f);

    // 3) softmax rows
    softmax_kernel<<<BB * SS, 256>>>(S);

    // 4) O = P @ V
    dim3 go(DD / BN, SS / BM, BB);
    gemm_kernel<false><<<go, 256>>>(S, V, out, SS, DD, SS,
                                    (size_t)SS * SS, (size_t)SS * DD,
                                    (size_t)SS * DD, 1.0f);
}

// round 3
// speedup vs baseline: 2.2339x; 2.2339x over previous
#include <cuda_runtime.h>
#include <cuda_bf16.h>
#include <cstdint>

// Shapes (fixed): B=4, S=2048, D=1024
#define BB 4
#define SS 2048
#define DD 1024
#define MQKV (BB * SS)            // 8192

// ---- GEMM tile config (mma.sync path; portable ISA only) ----
#define BM 128
#define BN 128
#define BK 32                     // bf16 K elems per stage
#define PITCH 80                  // smem bytes per row (64 data + 16 pad)
#define TILE_B   (128 * PITCH)    // 10240
#define STAGE_B  (4 * TILE_B)     // Ah, Al, Bh, Bl = 40960
#define SMEM_TOTAL (2 * STAGE_B)  // 81920 (double buffer)
#define NT 128                    // 4 warps

// ---------------- scratch (device globals; allocation-free rule) -----------
__device__ __align__(256) __nv_bfloat16 g_xh[(size_t)MQKV * DD];
__device__ __align__(256) __nv_bfloat16 g_xl[(size_t)MQKV * DD];
__device__ __align__(256) __nv_bfloat16 g_Wth[3][(size_t)DD * DD];
__device__ __align__(256) __nv_bfloat16 g_Wtl[3][(size_t)DD * DD];
__device__ __align__(256) float         g_F[(size_t)MQKV * DD];      // fp32 staging
__device__ __align__(256) __nv_bfloat16 g_Qh[(size_t)MQKV * DD];
__device__ __align__(256) __nv_bfloat16 g_Ql[(size_t)MQKV * DD];
__device__ __align__(256) __nv_bfloat16 g_Kh[(size_t)MQKV * DD];
__device__ __align__(256) __nv_bfloat16 g_Kl[(size_t)MQKV * DD];
__device__ __align__(256) __nv_bfloat16 g_Vth[(size_t)DD * MQKV];    // V^T [D, B*S]
__device__ __align__(256) __nv_bfloat16 g_Vtl[(size_t)DD * MQKV];
__device__ __align__(256) float         g_S[(size_t)BB * SS * SS];   // scores fp32
__device__ __align__(256) __nv_bfloat16 g_Ph[(size_t)BB * SS * SS];
__device__ __align__(256) __nv_bfloat16 g_Pl[(size_t)BB * SS * SS];

// ---------------- PTX helpers ----------------------------------------------
__device__ __forceinline__ uint32_t smem_u32(const void* p) {
    uint32_t a;
    asm("{ .reg .u64 t; cvta.to.shared.u64 t, %1; cvt.u32.u64 %0, t; }"
        : "=r"(a) : "l"(p));
    return a;
}
__device__ __forceinline__ void cpa16(uint32_t dst, const void* src) {
    asm volatile("cp.async.cg.shared.global [%0], [%1], 16;"
                 :: "r"(dst), "l"(src));
}
#define CP_COMMIT() asm volatile("cp.async.commit_group;" ::: "memory")
#define CP_WAIT1()  asm volatile("cp.async.wait_group 1;" ::: "memory")
#define CP_WAIT0()  asm volatile("cp.async.wait_group 0;" ::: "memory")

#define LDSM4(r, addr)                                                      \
    asm volatile("ldmatrix.sync.aligned.m8n8.x4.shared.b16 {%0,%1,%2,%3}, [%4];" \
        : "=r"((r)[0]), "=r"((r)[1]), "=r"((r)[2]), "=r"((r)[3]) : "r"(addr))

#define MMA(c, a, b0, b1)                                                   \
    asm volatile("mma.sync.aligned.m16n8k16.row.col.f32.bf16.bf16.f32 "     \
        "{%0,%1,%2,%3}, {%4,%5,%6,%7}, {%8,%9}, {%0,%1,%2,%3};"             \
        : "+f"((c)[0]), "+f"((c)[1]), "+f"((c)[2]), "+f"((c)[3])            \
        : "r"((a)[0]), "r"((a)[1]), "r"((a)[2]), "r"((a)[3]),               \
          "r"(b0), "r"(b1))

// ---------------------------------------------------------------------------
// Split-bf16 HMMA GEMM:  C[M,N] = alpha * (Ah+Al)[M,K] @ (Bh+Bl)[N,K]^T
// 3-term: hi*hi + hi*lo + lo*hi, fp32 accumulate.
// Grid (N/128, M/128, batch). 128 threads, 4 warps of 64x64.
// ---------------------------------------------------------------------------
__global__ __launch_bounds__(NT, 2)
void mma_gemm(const __nv_bfloat16* __restrict__ Ah, const __nv_bfloat16* __restrict__ Al,
              const __nv_bfloat16* __restrict__ Bh, const __nv_bfloat16* __restrict__ Bl,
              float* __restrict__ C,
              int K, int lda, int ldb, int ldc,
              size_t strideA, size_t strideB, size_t strideC,
              float alpha)
{
    extern __shared__ char smem[];
    const uint32_t sbase = smem_u32(smem);
    const int tid  = threadIdx.x;
    const int lane = tid & 31, wid = tid >> 5;
    const int bz = blockIdx.z;
    Ah += (size_t)bz * strideA;  Al += (size_t)bz * strideA;
    Bh += (size_t)bz * strideB;  Bl += (size_t)bz * strideB;
    C  += (size_t)bz * strideC;
    const int tileM = blockIdx.y * BM;
    const int tileN = blockIdx.x * BN;

    const int wm = (wid >> 1) * 64;        // warp M offset
    const int wn = (wid & 1) * 64;         // warp N offset

    // ldmatrix per-lane row/col (bytes) inside a tile
    const int a_row = wm + (lane & 15);
    const int a_col = (lane >> 4) * 16;
    const int b_row = wn + (lane & 7) + (lane >> 4) * 8;
    const int b_col = ((lane >> 3) & 1) * 16;

    float acc[4][8][4];
    #pragma unroll
    for (int i = 0; i < 4; i++)
        #pragma unroll
        for (int j = 0; j < 8; j++)
            #pragma unroll
            for (int r = 0; r < 4; r++) acc[i][j][r] = 0.0f;

    auto load_stage = [&](int s) {
        const uint32_t buf = sbase + (uint32_t)(s & 1) * STAGE_B;
        const int kt = s * BK;
        #pragma unroll
        for (int i = 0; i < 16; i++) {
            int g    = i * NT + tid;        // 0..2047 16B chunks
            int tile = g >> 9;              // 0:Ah 1:Al 2:Bh 3:Bl
            int loc  = g & 511;
            int row  = loc >> 2, ch = loc & 3;
            const __nv_bfloat16* src;
            if      (tile == 0) src = Ah + (size_t)(tileM + row) * lda + kt + ch * 8;
            else if (tile == 1) src = Al + (size_t)(tileM + row) * lda + kt + ch * 8;
            else if (tile == 2) src = Bh + (size_t)(tileN + row) * ldb + kt + ch * 8;
            else                src = Bl + (size_t)(tileN + row) * ldb + kt + ch * 8;
            cpa16(buf + (uint32_t)tile * TILE_B + (uint32_t)(row * PITCH + ch * 16), src);
        }
        CP_COMMIT();
    };

    const int nst = K / BK;
    load_stage(0);
    load_stage(1);

    for (int s = 0; s < nst; s++) {
        if (s == nst - 1) { CP_WAIT0(); } else { CP_WAIT1(); }
        __syncthreads();
        const uint32_t buf = sbase + (uint32_t)(s & 1) * STAGE_B;

        #pragma unroll
        for (int ks = 0; ks < 2; ks++) {
            const uint32_t kb = ks * 32;    // 16 bf16 = 32 bytes
            uint32_t ah[4][4], al[4][4], bh[4][4], bl[4][4];
            #pragma unroll
            for (int mt = 0; mt < 4; mt++) {
                uint32_t ra = buf + (uint32_t)((a_row + mt * 16) * PITCH) + kb + a_col;
                LDSM4(ah[mt], ra);
                LDSM4(al[mt], ra + TILE_B);
            }
            #pragma unroll
            for (int j = 0; j < 4; j++) {
                uint32_t rb = buf + 2 * TILE_B
                            + (uint32_t)((b_row + j * 16) * PITCH) + kb + b_col;
                LDSM4(bh[j], rb);
                LDSM4(bl[j], rb + TILE_B);
            }
            #pragma unroll
            for (int mt = 0; mt < 4; mt++) {
                #pragma unroll
                for (int j = 0; j < 4; j++) {
                    MMA(acc[mt][2 * j],     ah[mt], bh[j][0], bh[j][1]);
                    MMA(acc[mt][2 * j + 1], ah[mt], bh[j][2], bh[j][3]);
                    MMA(acc[mt][2 * j],     ah[mt], bl[j][0], bl[j][1]);
                    MMA(acc[mt][2 * j + 1], ah[mt], bl[j][2], bl[j][3]);
                    MMA(acc[mt][2 * j],     al[mt], bh[j][0], bh[j][1]);
                    MMA(acc[mt][2 * j + 1], al[mt], bh[j][2], bh[j][3]);
                }
            }
        }
        __syncthreads();
        if (s + 2 < nst) load_stage(s + 2);
    }

    // ---- epilogue: registers -> gmem ----
    const int er = lane >> 2;              // 0..7
    const int ec = (lane & 3) * 2;         // 0,2,4,6
    #pragma unroll
    for (int mt = 0; mt < 4; mt++) {
        const size_t r0 = (size_t)(tileM + wm + mt * 16 + er);
        #pragma unroll
        for (int j = 0; j < 8; j++) {
            const int col = tileN + wn + j * 8 + ec;
            float2 v0 = make_float2(acc[mt][j][0] * alpha, acc[mt][j][1] * alpha);
            float2 v1 = make_float2(acc[mt][j][2] * alpha, acc[mt][j][3] * alpha);
            *reinterpret_cast<float2*>(&C[r0 * ldc + col])       = v0;
            *reinterpret_cast<float2*>(&C[(r0 + 8) * ldc + col]) = v1;
        }
    }
}

// ---------------------------------------------------------------------------
// fp32 -> (hi, lo) bf16 split, elementwise
// ---------------------------------------------------------------------------
__global__ __launch_bounds__(256)
void split_kernel(const float* __restrict__ in,
                  __nv_bfloat16* __restrict__ hi, __nv_bfloat16* __restrict__ lo,
                  size_t n4)
{
    size_t i = (size_t)blockIdx.x * blockDim.x + threadIdx.x;
    if (i >= n4) return;
    float4 v = reinterpret_cast<const float4*>(in)[i];
    __nv_bfloat16 h0 = __float2bfloat16(v.x), h1 = __float2bfloat16(v.y);
    __nv_bfloat16 h2 = __float2bfloat16(v.z), h3 = __float2bfloat16(v.w);
    __nv_bfloat162 hA; hA.x = h0; hA.y = h1;
    __nv_bfloat162 hB; hB.x = h2; hB.y = h3;
    __nv_bfloat162 lA, lB;
    lA.x = __float2bfloat16(v.x - __bfloat162float(h0));
    lA.y = __float2bfloat16(v.y - __bfloat162float(h1));
    lB.x = __float2bfloat16(v.z - __bfloat162float(h2));
    lB.y = __float2bfloat16(v.w - __bfloat162float(h3));
    reinterpret_cast<__nv_bfloat162*>(hi)[2 * i]     = hA;
    reinterpret_cast<__nv_bfloat162*>(hi)[2 * i + 1] = hB;
    reinterpret_cast<__nv_bfloat162*>(lo)[2 * i]     = lA;
    reinterpret_cast<__nv_bfloat162*>(lo)[2 * i + 1] = lB;
}

// ---------------------------------------------------------------------------
// fp32 [R,C] -> transposed (hi, lo) bf16 [C,R]
// ---------------------------------------------------------------------------
__global__ __launch_bounds__(256)
void tsplit_kernel(const float* __restrict__ in,
                   __nv_bfloat16* __restrict__ hi, __nv_bfloat16* __restrict__ lo,
                   int R, int C)
{
    __shared__ float tile[32][33];
    const int c0 = blockIdx.x * 32, r0 = blockIdx.y * 32;
    const int tx = threadIdx.x, ty = threadIdx.y;   // 32 x 8
    #pragma unroll
    for (int j = 0; j < 32; j += 8)
        tile[ty + j][tx] = in[(size_t)(r0 + ty + j) * C + c0 + tx];
    __syncthreads();
    #pragma unroll
    for (int j = 0; j < 32; j += 8) {
        float v = tile[tx][ty + j];
        __nv_bfloat16 h = __float2bfloat16(v);
        size_t o = (size_t)(c0 + ty + j) * R + r0 + tx;
        hi[o] = h;
        lo[o] = __float2bfloat16(v - __bfloat162float(h));
    }
}

// ---------------------------------------------------------------------------
// Row softmax over 2048 cols -> (hi, lo) bf16 probabilities
// ---------------------------------------------------------------------------
__global__ __launch_bounds__(256)
void softmax_kernel(const float* __restrict__ S,
                    __nv_bfloat16* __restrict__ Ph, __nv_bfloat16* __restrict__ Pl)
{
    __shared__ float sh[8];
    const size_t base = (size_t)blockIdx.x * SS;
    const int tid = threadIdx.x;
    const float4* rowp = reinterpret_cast<const float4*>(S + base);

    float4 v0 = rowp[tid];
    float4 v1 = rowp[tid + 256];

    float m = fmaxf(fmaxf(fmaxf(v0.x, v0.y), fmaxf(v0.z, v0.w)),
                    fmaxf(fmaxf(v1.x, v1.y), fmaxf(v1.z, v1.w)));
    #pragma unroll
    for (int o = 16; o > 0; o >>= 1) m = fmaxf(m, __shfl_xor_sync(~0u, m, o));
    if ((tid & 31) == 0) sh[tid >> 5] = m;
    __syncthreads();
    m = sh[tid & 7];
    #pragma unroll
    for (int o = 4; o > 0; o >>= 1) m = fmaxf(m, __shfl_xor_sync(~0u, m, o));
    __syncthreads();

    v0.x = __expf(v0.x - m); v0.y = __expf(v0.y - m);
    v0.z = __expf(v0.z - m); v0.w = __expf(v0.w - m);
    v1.x = __expf(v1.x - m); v1.y = __expf(v1.y - m);
    v1.z = __expf(v1.z - m); v1.w = __expf(v1.w - m);

    float s = (v0.x + v0.y + v0.z + v0.w) + (v1.x + v1.y + v1.z + v1.w);
    #pragma unroll
    for (int o = 16; o > 0; o >>= 1) s += __shfl_xor_sync(~0u, s, o);
    if ((tid & 31) == 0) sh[tid >> 5] = s;
    __syncthreads();
    s = sh[tid & 7];
    #pragma unroll
    for (int o = 4; o > 0; o >>= 1) s += __shfl_xor_sync(~0u, s, o);

    const float inv = 1.0f / s;
    v0.x *= inv; v0.y *= inv; v0.z *= inv; v0.w *= inv;
    v1.x *= inv; v1.y *= inv; v1.z *= inv; v1.w *= inv;

    __nv_bfloat162* ph = reinterpret_cast<__nv_bfloat162*>(Ph + base);
    __nv_bfloat162* pl = reinterpret_cast<__nv_bfloat162*>(Pl + base);
    float vs[8] = {v0.x, v0.y, v0.z, v0.w, v1.x, v1.y, v1.z, v1.w};
    #pragma unroll
    for (int h = 0; h < 2; h++) {
        int colpair = (h == 0) ? tid * 2 : (tid + 256) * 2;
        #pragma unroll
        for (int j = 0; j < 2; j++) {
            float a = vs[h * 4 + 2 * j], bb = vs[h * 4 + 2 * j + 1];
            __nv_bfloat162 hh, ll;
            hh.x = __float2bfloat16(a);  hh.y = __float2bfloat16(bb);
            ll.x = __float2bfloat16(a - __bfloat162float(hh.x));
            ll.y = __float2bfloat16(bb - __bfloat162float(hh.y));
            ph[colpair + j] = hh;
            pl[colpair + j] = ll;
        }
    }
}

// ---------------------------------------------------------------------------
// Launch
// ---------------------------------------------------------------------------
extern "C" void kernel_launch(void* const* d_in, const int* in_sizes, int n_in,
                              void* d_out, int out_size)
{
    const float* x  = (const float*)d_in[0];
    const float* WQ = (const float*)d_in[1];
    const float* WK = (const float*)d_in[2];
    const float* WV = (const float*)d_in[3];
    float* out = (float*)d_out;

    __nv_bfloat16 *xh, *xl, *Wth, *Wtl, *Qh, *Ql, *Kh, *Kl, *Vth, *Vtl, *Ph, *Pl;
    float *F, *Smat;
    cudaGetSymbolAddress((void**)&xh,  g_xh);
    cudaGetSymbolAddress((void**)&xl,  g_xl);
    cudaGetSymbolAddress((void**)&Wth, g_Wth);
    cudaGetSymbolAddress((void**)&Wtl, g_Wtl);
    cudaGetSymbolAddress((void**)&F,   g_F);
    cudaGetSymbolAddress((void**)&Qh,  g_Qh);
    cudaGetSymbolAddress((void**)&Ql,  g_Ql);
    cudaGetSymbolAddress((void**)&Kh,  g_Kh);
    cudaGetSymbolAddress((void**)&Kl,  g_Kl);
    cudaGetSymbolAddress((void**)&Vth, g_Vth);
    cudaGetSymbolAddress((void**)&Vtl, g_Vtl);
    cudaGetSymbolAddress((void**)&Smat, g_S);
    cudaGetSymbolAddress((void**)&Ph,  g_Ph);
    cudaGetSymbolAddress((void**)&Pl,  g_Pl);

    cudaFuncSetAttribute(mma_gemm, cudaFuncAttributeMaxDynamicSharedMemorySize, SMEM_TOTAL);

    const size_t nW  = (size_t)DD * DD;
    const size_t n4x = (size_t)MQKV * DD / 4;

    // 1) input conversions
    split_kernel<<<(unsigned)((n4x + 255) / 256), 256>>>(x, xh, xl, n4x);
    dim3 tb(32, 8);
    tsplit_kernel<<<dim3(DD / 32, DD / 32), tb>>>(WQ, Wth + 0 * nW, Wtl + 0 * nW, DD, DD);
    tsplit_kernel<<<dim3(DD / 32, DD / 32), tb>>>(WK, Wth + 1 * nW, Wtl + 1 * nW, DD, DD);
    tsplit_kernel<<<dim3(DD / 32, DD / 32), tb>>>(WV, Wth + 2 * nW, Wtl + 2 * nW, DD, DD);

    // 2) projections (fp32 staging, then split)
    dim3 gp(DD / BN, MQKV / BM, 1);                     // 8 x 64
    mma_gemm<<<gp, NT, SMEM_TOTAL>>>(xh, xl, Wth + 0 * nW, Wtl + 0 * nW, F,
                                     DD, DD, DD, DD, 0, 0, 0, 1.0f);
    split_kernel<<<(unsigned)((n4x + 255) / 256), 256>>>(F, Qh, Ql, n4x);
    mma_gemm<<<gp, NT, SMEM_TOTAL>>>(xh, xl, Wth + 1 * nW, Wtl + 1 * nW, F,
                                     DD, DD, DD, DD, 0, 0, 0, 1.0f);
    split_kernel<<<(unsigned)((n4x + 255) / 256), 256>>>(F, Kh, Kl, n4x);
    mma_gemm<<<gp, NT, SMEM_TOTAL>>>(xh, xl, Wth + 2 * nW, Wtl + 2 * nW, F,
                                     DD, DD, DD, DD, 0, 0, 0, 1.0f);
    tsplit_kernel<<<dim3(DD / 32, MQKV / 32), tb>>>(F, Vth, Vtl, MQKV, DD);

    // 3) scores: S = Q @ K^T / 32  (per batch)
    dim3 gs(SS / BN, SS / BM, BB);                      // 16 x 16 x 4
    mma_gemm<<<gs, NT, SMEM_TOTAL>>>(Qh, Ql, Kh, Kl, Smat,
                                     DD, DD, DD, SS,
                                     (size_t)SS * DD, (size_t)SS * DD,
                                     (size_t)SS * SS, 1.0f / 32.0f);

    // 4) softmax -> split-bf16 probabilities
    softmax_kernel<<<BB * SS, 256>>>(Smat, Ph, Pl);

    // 5) O = P @ V  (B operand = V^T rows, K along sequence)
    dim3 go(DD / BN, SS / BM, BB);                      // 8 x 16 x 4
    mma_gemm<<<go, NT, SMEM_TOTAL>>>(Ph, Pl, Vth, Vtl, out,
                                     SS, SS, MQKV, DD,
                                     (size_t)SS * SS, (size_t)SS,
                                     (size_t)SS * DD, 1.0f);
}